// round 3
// baseline (speedup 1.0000x reference)
#include <cuda_runtime.h>
#include <math.h>

#define TT 4096
#define DD 1024
#define NCTA 128
#define STH 256   // scan threads: 8 warps, 1 warp per output column (8 cols/CTA)

// ---------------- scratch (device globals: no allocation allowed) ----------------
__device__ float g_Ar[TT * DD];   // xs@Wir + bir
__device__ float g_Az[TT * DD];   // xs@Wiz + biz
__device__ float g_An[TT * DD];   // xs@Win + bin
__device__ float g_ys[TT * DD];   // scan outputs
__device__ float g_lin[TT * DD];  // xs + relu(ys)@Wl + bl (pre-LN)
__device__ float g_h[2][DD];      // ping-pong hidden state
__device__ unsigned g_count;      // grid barrier counter

// ---------------- helpers ----------------
__device__ __forceinline__ float4 ldcg4(const float4* p) {
    float4 v;
    asm volatile("ld.global.cg.v4.f32 {%0,%1,%2,%3}, [%4];"
                 : "=f"(v.x), "=f"(v.y), "=f"(v.z), "=f"(v.w) : "l"(p));
    return v;
}
__device__ __forceinline__ unsigned ld_acquire_u32(const unsigned* p) {
    unsigned v;
    asm volatile("ld.acquire.gpu.global.u32 %0, [%1];" : "=r"(v) : "l"(p));
    return v;
}

// ---------------- persistent GRU scan ----------------
// 128 CTAs, each owns 8 columns j = cta*8 + w (one warp per column, all 3 gates).
// Recurrent weight columns live in SMEM for the entire scan.
__global__ void __launch_bounds__(STH, 1) scan_kernel(
    const float* __restrict__ Whr, const float* __restrict__ Whz,
    const float* __restrict__ Whn, const float* __restrict__ bhn)
{
    extern __shared__ float smem[];
    float* Ws = smem;              // [3][8][DD] gate-major, column-major-per-col
    float* hs = smem + 3 * 8 * DD; // [DD] current hidden state

    const int tid   = threadIdx.x;
    const int cta   = blockIdx.x;
    const int jbase = cta * 8;
    const int w     = tid >> 5;
    const int lane  = tid & 31;
    const int j     = jbase + w;

    // one-time weight load: column j of each gate matrix -> SMEM
    {
        const float* Wsrc[3] = {Whr, Whz, Whn};
        for (int g = 0; g < 3; ++g) {
            const float* W = Wsrc[g];
            float* dst = Ws + g * (8 * DD);
            for (int idx = tid; idx < 8 * DD; idx += STH) {
                const int jj = idx & 7;
                const int k  = idx >> 3;
                dst[jj * DD + k] = W[k * DD + jbase + jj]; // 32B/row per CTA, sector-aligned
            }
        }
    }
    const float bh = bhn[j];
    const float4* Wr4 = (const float4*)(Ws + 0 * (8 * DD) + w * DD);
    const float4* Wz4 = (const float4*)(Ws + 1 * (8 * DD) + w * DD);
    const float4* Wn4 = (const float4*)(Ws + 2 * (8 * DD) + w * DD);
    const float4* hs4 = (const float4*)hs;
    __syncthreads();

    for (int t = 0; t < TT; ++t) {
        // load h (written by all CTAs last step) -> SMEM. MUST bypass L1 (.cg):
        // L1 may hold a stale copy of this ping-pong buffer from step t-2.
        ((float4*)hs)[tid] = ldcg4(((const float4*)g_h[t & 1]) + tid);
        __syncthreads();

        // prefetch input-projection terms for this (t, j); latency hides under dot
        float ar = 0.f, az = 0.f, an = 0.f;
        if (lane == 0) {
            ar = g_Ar[t * DD + j];
            az = g_Az[t * DD + j];
            an = g_An[t * DD + j];
        }

        // 3 dot products of length 1024, vectorized float4, one warp per column
        float accr = 0.f, accz = 0.f, accn = 0.f;
        #pragma unroll
        for (int i = 0; i < 8; ++i) {
            const int k4 = lane + i * 32;
            const float4 hv = hs4[k4];
            const float4 wr = Wr4[k4];
            const float4 wz = Wz4[k4];
            const float4 wn = Wn4[k4];
            accr = fmaf(hv.x, wr.x, fmaf(hv.y, wr.y, fmaf(hv.z, wr.z, fmaf(hv.w, wr.w, accr))));
            accz = fmaf(hv.x, wz.x, fmaf(hv.y, wz.y, fmaf(hv.z, wz.z, fmaf(hv.w, wz.w, accz))));
            accn = fmaf(hv.x, wn.x, fmaf(hv.y, wn.y, fmaf(hv.z, wn.z, fmaf(hv.w, wn.w, accn))));
        }
        #pragma unroll
        for (int off = 16; off > 0; off >>= 1) {
            accr += __shfl_xor_sync(0xffffffffu, accr, off);
            accz += __shfl_xor_sync(0xffffffffu, accz, off);
            accn += __shfl_xor_sync(0xffffffffu, accn, off);
        }
        if (lane == 0) {
            const float hprev = hs[j];
            const float r  = 1.f / (1.f + __expf(-(ar + accr)));
            const float z  = 1.f / (1.f + __expf(-(az + accz)));
            const float n  = tanhf(an + r * (accn + bh));
            const float hn = (1.f - z) * n + z * hprev;
            g_h[(t + 1) & 1][j] = hn;
            g_ys[t * DD + j]    = hn;
        }
        __syncthreads();               // all CTA writes done + hs reads done

        // grid barrier: release(fence)+relaxed add, acquire-spin, fence
        if (tid == 0) {
            __threadfence();                       // publish this CTA's h writes
            atomicAdd(&g_count, 1u);
            const unsigned target = (unsigned)(t + 1) * NCTA;
            while (ld_acquire_u32(&g_count) < target) { }
            __threadfence();                       // order subsequent h loads
        }
        __syncthreads();
    }
}

// ---------------- fp32 SGEMM: C[M,N] = op(A)[M,K] @ B[K,N] + bias (+ resid) ----------------
// 128x128 tile, BK=8, 256 threads, 8x8 micro-tile. op = optional relu on A.
template <bool RELU, bool RESID>
__global__ void __launch_bounds__(256) sgemm_kernel(
    const float* __restrict__ A, const float* __restrict__ B,
    const float* __restrict__ bias, const float* __restrict__ resid,
    float* __restrict__ C, int M, int N, int K)
{
    __shared__ float As[8][128];
    __shared__ float Bs[8][128];
    const int tid = threadIdx.x;
    const int bx = blockIdx.x, by = blockIdx.y;

    const int arow = tid >> 1;         // 0..127
    const int acol = (tid & 1) << 2;   // 0 or 4
    const int brow = tid >> 5;         // 0..7
    const int bcol = (tid & 31) << 2;  // 0..124
    const int tx = tid & 15;
    const int ty = tid >> 4;

    const float* Ab = A + (size_t)by * 128 * K;
    const float* Bb = B + bx * 128;

    float acc[8][8];
    #pragma unroll
    for (int i = 0; i < 8; ++i)
        #pragma unroll
        for (int jj = 0; jj < 8; ++jj) acc[i][jj] = 0.f;

    float4 aReg = *(const float4*)(Ab + (size_t)arow * K + acol);
    float4 bReg = *(const float4*)(Bb + (size_t)brow * N + bcol);

    for (int k0 = 0; k0 < K; k0 += 8) {
        float4 av = aReg;
        if (RELU) {
            av.x = fmaxf(av.x, 0.f); av.y = fmaxf(av.y, 0.f);
            av.z = fmaxf(av.z, 0.f); av.w = fmaxf(av.w, 0.f);
        }
        As[acol + 0][arow] = av.x;
        As[acol + 1][arow] = av.y;
        As[acol + 2][arow] = av.z;
        As[acol + 3][arow] = av.w;
        *(float4*)&Bs[brow][bcol] = bReg;
        __syncthreads();
        if (k0 + 8 < K) {   // prefetch next tile during compute
            aReg = *(const float4*)(Ab + (size_t)arow * K + (k0 + 8) + acol);
            bReg = *(const float4*)(Bb + (size_t)(k0 + 8 + brow) * N + bcol);
        }
        #pragma unroll
        for (int kk = 0; kk < 8; ++kk) {
            float a[8], b[8];
            *(float4*)&a[0] = *(const float4*)&As[kk][ty * 8];
            *(float4*)&a[4] = *(const float4*)&As[kk][ty * 8 + 4];
            *(float4*)&b[0] = *(const float4*)&Bs[kk][tx * 8];
            *(float4*)&b[4] = *(const float4*)&Bs[kk][tx * 8 + 4];
            #pragma unroll
            for (int i = 0; i < 8; ++i)
                #pragma unroll
                for (int jj = 0; jj < 8; ++jj)
                    acc[i][jj] = fmaf(a[i], b[jj], acc[i][jj]);
        }
        __syncthreads();
    }

    const int nbase = bx * 128 + tx * 8;
    const float4 b0 = *(const float4*)(bias + nbase);
    const float4 b1 = *(const float4*)(bias + nbase + 4);
    #pragma unroll
    for (int i = 0; i < 8; ++i) {
        const int m = by * 128 + ty * 8 + i;
        float4 c0, c1;
        c0.x = acc[i][0] + b0.x; c0.y = acc[i][1] + b0.y;
        c0.z = acc[i][2] + b0.z; c0.w = acc[i][3] + b0.w;
        c1.x = acc[i][4] + b1.x; c1.y = acc[i][5] + b1.y;
        c1.z = acc[i][6] + b1.z; c1.w = acc[i][7] + b1.w;
        if (RESID) {
            const float4 r0 = *(const float4*)(resid + (size_t)m * N + nbase);
            const float4 r1 = *(const float4*)(resid + (size_t)m * N + nbase + 4);
            c0.x += r0.x; c0.y += r0.y; c0.z += r0.z; c0.w += r0.w;
            c1.x += r1.x; c1.y += r1.y; c1.z += r1.z; c1.w += r1.w;
        }
        *(float4*)(C + (size_t)m * N + nbase)     = c0;
        *(float4*)(C + (size_t)m * N + nbase + 4) = c1;
    }
}

// ---------------- layernorm over last dim ----------------
__global__ void __launch_bounds__(256) ln_kernel(
    const float* __restrict__ lin, const float* __restrict__ scale,
    const float* __restrict__ bias, float* __restrict__ out)
{
    const int t = blockIdx.x;
    const int tid = threadIdx.x;
    const int w = tid >> 5, lane = tid & 31;
    const float4 v = ((const float4*)(lin + (size_t)t * DD))[tid];
    float s = v.x + v.y + v.z + v.w;
    float q = v.x * v.x + v.y * v.y + v.z * v.z + v.w * v.w;
    #pragma unroll
    for (int off = 16; off > 0; off >>= 1) {
        s += __shfl_xor_sync(0xffffffffu, s, off);
        q += __shfl_xor_sync(0xffffffffu, q, off);
    }
    __shared__ float ss[8], qs[8];
    __shared__ float sMean, sInv;
    if (lane == 0) { ss[w] = s; qs[w] = q; }
    __syncthreads();
    if (tid == 0) {
        float S = 0.f, Q = 0.f;
        #pragma unroll
        for (int i = 0; i < 8; ++i) { S += ss[i]; Q += qs[i]; }
        const float mean = S * (1.0f / DD);
        const float var  = Q * (1.0f / DD) - mean * mean;
        sMean = mean;
        sInv  = rsqrtf(var + 1e-6f);
    }
    __syncthreads();
    const float mean = sMean, inv = sInv;
    const float4 sc = ((const float4*)scale)[tid];
    const float4 bi = ((const float4*)bias)[tid];
    float4 o;
    o.x = (v.x - mean) * inv * sc.x + bi.x;
    o.y = (v.y - mean) * inv * sc.y + bi.y;
    o.z = (v.z - mean) * inv * sc.z + bi.z;
    o.w = (v.w - mean) * inv * sc.w + bi.w;
    ((float4*)(out + (size_t)t * DD))[tid] = o;
}

// ---------------- launch ----------------
extern "C" void kernel_launch(void* const* d_in, const int* in_sizes, int n_in,
                              void* d_out, int out_size) {
    (void)in_sizes; (void)n_in; (void)out_size;
    const float* xs   = (const float*)d_in[0];
    const float* hini = (const float*)d_in[1];
    const float* Wir  = (const float*)d_in[2];
    const float* Wiz  = (const float*)d_in[3];
    const float* Win  = (const float*)d_in[4];
    const float* bir  = (const float*)d_in[5];
    const float* biz  = (const float*)d_in[6];
    const float* bin_ = (const float*)d_in[7];
    const float* Whr  = (const float*)d_in[8];
    const float* Whz  = (const float*)d_in[9];
    const float* Whn  = (const float*)d_in[10];
    const float* bhn  = (const float*)d_in[11];
    const float* Wl   = (const float*)d_in[12];
    const float* bl   = (const float*)d_in[13];
    const float* lns  = (const float*)d_in[14];
    const float* lnb  = (const float*)d_in[15];
    float* out = (float*)d_out;

    float *Ar, *Az, *An, *ys, *lin, *hb;
    unsigned* cnt;
    cudaGetSymbolAddress((void**)&Ar,  g_Ar);
    cudaGetSymbolAddress((void**)&Az,  g_Az);
    cudaGetSymbolAddress((void**)&An,  g_An);
    cudaGetSymbolAddress((void**)&ys,  g_ys);
    cudaGetSymbolAddress((void**)&lin, g_lin);
    cudaGetSymbolAddress((void**)&hb,  g_h);
    cudaGetSymbolAddress((void**)&cnt, g_count);

    // per-replay state reset (device globals persist across graph replays!)
    cudaMemsetAsync(cnt, 0, sizeof(unsigned), 0);
    cudaMemcpyAsync(hb, hini, DD * sizeof(float), cudaMemcpyDeviceToDevice, 0);

    // input projections (bias fused)
    dim3 grid(DD / 128, TT / 128);
    sgemm_kernel<false, false><<<grid, 256>>>(xs, Wir, bir,  nullptr, Ar, TT, DD, DD);
    sgemm_kernel<false, false><<<grid, 256>>>(xs, Wiz, biz,  nullptr, Az, TT, DD, DD);
    sgemm_kernel<false, false><<<grid, 256>>>(xs, Win, bin_, nullptr, An, TT, DD, DD);

    // persistent scan
    const int smem = (3 * 8 * DD + DD) * (int)sizeof(float);  // 102400 B
    cudaFuncSetAttribute(scan_kernel, cudaFuncAttributeMaxDynamicSharedMemorySize, smem);
    scan_kernel<<<NCTA, STH, smem>>>(Whr, Whz, Whn, bhn);

    // out dense: lin = xs + relu(ys)@Wl + bl, then LN
    sgemm_kernel<true, true><<<grid, 256>>>(ys, Wl, bl, xs, lin, TT, DD, DD);
    ln_kernel<<<TT, 256>>>(lin, lns, lnb, out);
}

// round 4
// speedup vs baseline: 1.0027x; 1.0027x over previous
#include <cuda_runtime.h>
#include <math.h>

#define TT 4096
#define DD 1024
#define NCTA 128
#define STH 256   // scan threads: 8 warps, 1 warp per output column (8 cols/CTA)

// ---------------- scratch (device globals: no allocation allowed) ----------------
__device__ float g_Ar[TT * DD];   // xs@Wir + bir
__device__ float g_Az[TT * DD];   // xs@Wiz + biz
__device__ float g_An[TT * DD];   // xs@Win + bin
__device__ float g_ys[TT * DD];   // scan outputs
__device__ float g_lin[TT * DD];  // xs + relu(ys)@Wl + bl (pre-LN)
__device__ float g_h[2][DD];      // ping-pong hidden state
__device__ unsigned g_count;      // grid barrier counter

// ---------------- helpers ----------------
__device__ __forceinline__ float4 ldcg4(const float4* p) {
    float4 v;
    asm volatile("ld.global.cg.v4.f32 {%0,%1,%2,%3}, [%4];"
                 : "=f"(v.x), "=f"(v.y), "=f"(v.z), "=f"(v.w) : "l"(p));
    return v;
}
__device__ __forceinline__ unsigned ld_acquire_u32(const unsigned* p) {
    unsigned v;
    asm volatile("ld.acquire.gpu.global.u32 %0, [%1];" : "=r"(v) : "l"(p));
    return v;
}

// ---------------- persistent GRU scan ----------------
// 128 CTAs, each owns 8 columns j = cta*8 + w (one warp per column, all 3 gates).
// Recurrent weight columns live in SMEM for the entire scan.
__global__ void __launch_bounds__(STH, 1) scan_kernel(
    const float* __restrict__ Whr, const float* __restrict__ Whz,
    const float* __restrict__ Whn, const float* __restrict__ bhn)
{
    extern __shared__ float smem[];
    float* Ws = smem;              // [3][8][DD] gate-major, column-major-per-col
    float* hs = smem + 3 * 8 * DD; // [DD] current hidden state

    const int tid   = threadIdx.x;
    const int cta   = blockIdx.x;
    const int jbase = cta * 8;
    const int w     = tid >> 5;
    const int lane  = tid & 31;
    const int j     = jbase + w;

    // one-time weight load: column j of each gate matrix -> SMEM
    {
        const float* Wsrc[3] = {Whr, Whz, Whn};
        for (int g = 0; g < 3; ++g) {
            const float* W = Wsrc[g];
            float* dst = Ws + g * (8 * DD);
            for (int idx = tid; idx < 8 * DD; idx += STH) {
                const int jj = idx & 7;
                const int k  = idx >> 3;
                dst[jj * DD + k] = W[k * DD + jbase + jj]; // 32B/row per CTA, sector-aligned
            }
        }
    }
    const float bh = bhn[j];
    const float4* Wr4 = (const float4*)(Ws + 0 * (8 * DD) + w * DD);
    const float4* Wz4 = (const float4*)(Ws + 1 * (8 * DD) + w * DD);
    const float4* Wn4 = (const float4*)(Ws + 2 * (8 * DD) + w * DD);
    const float4* hs4 = (const float4*)hs;
    __syncthreads();

    for (int t = 0; t < TT; ++t) {
        // load h (written by all CTAs last step) -> SMEM. MUST bypass L1 (.cg):
        // L1 may hold a stale copy of this ping-pong buffer from step t-2.
        ((float4*)hs)[tid] = ldcg4(((const float4*)g_h[t & 1]) + tid);
        __syncthreads();

        // prefetch input-projection terms for this (t, j); latency hides under dot
        float ar = 0.f, az = 0.f, an = 0.f;
        if (lane == 0) {
            ar = g_Ar[t * DD + j];
            az = g_Az[t * DD + j];
            an = g_An[t * DD + j];
        }

        // 3 dot products of length 1024, vectorized float4, one warp per column
        float accr = 0.f, accz = 0.f, accn = 0.f;
        #pragma unroll
        for (int i = 0; i < 8; ++i) {
            const int k4 = lane + i * 32;
            const float4 hv = hs4[k4];
            const float4 wr = Wr4[k4];
            const float4 wz = Wz4[k4];
            const float4 wn = Wn4[k4];
            accr = fmaf(hv.x, wr.x, fmaf(hv.y, wr.y, fmaf(hv.z, wr.z, fmaf(hv.w, wr.w, accr))));
            accz = fmaf(hv.x, wz.x, fmaf(hv.y, wz.y, fmaf(hv.z, wz.z, fmaf(hv.w, wz.w, accz))));
            accn = fmaf(hv.x, wn.x, fmaf(hv.y, wn.y, fmaf(hv.z, wn.z, fmaf(hv.w, wn.w, accn))));
        }
        #pragma unroll
        for (int off = 16; off > 0; off >>= 1) {
            accr += __shfl_xor_sync(0xffffffffu, accr, off);
            accz += __shfl_xor_sync(0xffffffffu, accz, off);
            accn += __shfl_xor_sync(0xffffffffu, accn, off);
        }
        if (lane == 0) {
            const float hprev = hs[j];
            const float r  = 1.f / (1.f + __expf(-(ar + accr)));
            const float z  = 1.f / (1.f + __expf(-(az + accz)));
            const float n  = tanhf(an + r * (accn + bh));
            const float hn = (1.f - z) * n + z * hprev;
            g_h[(t + 1) & 1][j] = hn;
            g_ys[t * DD + j]    = hn;
        }
        __syncthreads();               // all CTA writes done + hs reads done

        // grid barrier: release(fence)+relaxed add, acquire-spin, fence
        if (tid == 0) {
            __threadfence();                       // publish this CTA's h writes
            atomicAdd(&g_count, 1u);
            const unsigned target = (unsigned)(t + 1) * NCTA;
            while (ld_acquire_u32(&g_count) < target) { }
            __threadfence();                       // order subsequent h loads
        }
        __syncthreads();
    }
}

// ---------------- fp32 SGEMM: C[M,N] = op(A)[M,K] @ B[K,N] + bias (+ resid) ----------------
// 128x128 tile, BK=8, 256 threads, 8x8 micro-tile. op = optional relu on A.
template <bool RELU, bool RESID>
__global__ void __launch_bounds__(256) sgemm_kernel(
    const float* __restrict__ A, const float* __restrict__ B,
    const float* __restrict__ bias, const float* __restrict__ resid,
    float* __restrict__ C, int M, int N, int K)
{
    __shared__ float As[8][128];
    __shared__ float Bs[8][128];
    const int tid = threadIdx.x;
    const int bx = blockIdx.x, by = blockIdx.y;

    const int arow = tid >> 1;         // 0..127
    const int acol = (tid & 1) << 2;   // 0 or 4
    const int brow = tid >> 5;         // 0..7
    const int bcol = (tid & 31) << 2;  // 0..124
    const int tx = tid & 15;
    const int ty = tid >> 4;

    const float* Ab = A + (size_t)by * 128 * K;
    const float* Bb = B + bx * 128;

    float acc[8][8];
    #pragma unroll
    for (int i = 0; i < 8; ++i)
        #pragma unroll
        for (int jj = 0; jj < 8; ++jj) acc[i][jj] = 0.f;

    float4 aReg = *(const float4*)(Ab + (size_t)arow * K + acol);
    float4 bReg = *(const float4*)(Bb + (size_t)brow * N + bcol);

    for (int k0 = 0; k0 < K; k0 += 8) {
        float4 av = aReg;
        if (RELU) {
            av.x = fmaxf(av.x, 0.f); av.y = fmaxf(av.y, 0.f);
            av.z = fmaxf(av.z, 0.f); av.w = fmaxf(av.w, 0.f);
        }
        As[acol + 0][arow] = av.x;
        As[acol + 1][arow] = av.y;
        As[acol + 2][arow] = av.z;
        As[acol + 3][arow] = av.w;
        *(float4*)&Bs[brow][bcol] = bReg;
        __syncthreads();
        if (k0 + 8 < K) {   // prefetch next tile during compute
            aReg = *(const float4*)(Ab + (size_t)arow * K + (k0 + 8) + acol);
            bReg = *(const float4*)(Bb + (size_t)(k0 + 8 + brow) * N + bcol);
        }
        #pragma unroll
        for (int kk = 0; kk < 8; ++kk) {
            float a[8], b[8];
            *(float4*)&a[0] = *(const float4*)&As[kk][ty * 8];
            *(float4*)&a[4] = *(const float4*)&As[kk][ty * 8 + 4];
            *(float4*)&b[0] = *(const float4*)&Bs[kk][tx * 8];
            *(float4*)&b[4] = *(const float4*)&Bs[kk][tx * 8 + 4];
            #pragma unroll
            for (int i = 0; i < 8; ++i)
                #pragma unroll
                for (int jj = 0; jj < 8; ++jj)
                    acc[i][jj] = fmaf(a[i], b[jj], acc[i][jj]);
        }
        __syncthreads();
    }

    const int nbase = bx * 128 + tx * 8;
    const float4 b0 = *(const float4*)(bias + nbase);
    const float4 b1 = *(const float4*)(bias + nbase + 4);
    #pragma unroll
    for (int i = 0; i < 8; ++i) {
        const int m = by * 128 + ty * 8 + i;
        float4 c0, c1;
        c0.x = acc[i][0] + b0.x; c0.y = acc[i][1] + b0.y;
        c0.z = acc[i][2] + b0.z; c0.w = acc[i][3] + b0.w;
        c1.x = acc[i][4] + b1.x; c1.y = acc[i][5] + b1.y;
        c1.z = acc[i][6] + b1.z; c1.w = acc[i][7] + b1.w;
        if (RESID) {
            const float4 r0 = *(const float4*)(resid + (size_t)m * N + nbase);
            const float4 r1 = *(const float4*)(resid + (size_t)m * N + nbase + 4);
            c0.x += r0.x; c0.y += r0.y; c0.z += r0.z; c0.w += r0.w;
            c1.x += r1.x; c1.y += r1.y; c1.z += r1.z; c1.w += r1.w;
        }
        *(float4*)(C + (size_t)m * N + nbase)     = c0;
        *(float4*)(C + (size_t)m * N + nbase + 4) = c1;
    }
}

// ---------------- layernorm over last dim ----------------
__global__ void __launch_bounds__(256) ln_kernel(
    const float* __restrict__ lin, const float* __restrict__ scale,
    const float* __restrict__ bias, float* __restrict__ out)
{
    const int t = blockIdx.x;
    const int tid = threadIdx.x;
    const int w = tid >> 5, lane = tid & 31;
    const float4 v = ((const float4*)(lin + (size_t)t * DD))[tid];
    float s = v.x + v.y + v.z + v.w;
    float q = v.x * v.x + v.y * v.y + v.z * v.z + v.w * v.w;
    #pragma unroll
    for (int off = 16; off > 0; off >>= 1) {
        s += __shfl_xor_sync(0xffffffffu, s, off);
        q += __shfl_xor_sync(0xffffffffu, q, off);
    }
    __shared__ float ss[8], qs[8];
    __shared__ float sMean, sInv;
    if (lane == 0) { ss[w] = s; qs[w] = q; }
    __syncthreads();
    if (tid == 0) {
        float S = 0.f, Q = 0.f;
        #pragma unroll
        for (int i = 0; i < 8; ++i) { S += ss[i]; Q += qs[i]; }
        const float mean = S * (1.0f / DD);
        const float var  = Q * (1.0f / DD) - mean * mean;
        sMean = mean;
        sInv  = rsqrtf(var + 1e-6f);
    }
    __syncthreads();
    const float mean = sMean, inv = sInv;
    const float4 sc = ((const float4*)scale)[tid];
    const float4 bi = ((const float4*)bias)[tid];
    float4 o;
    o.x = (v.x - mean) * inv * sc.x + bi.x;
    o.y = (v.y - mean) * inv * sc.y + bi.y;
    o.z = (v.z - mean) * inv * sc.z + bi.z;
    o.w = (v.w - mean) * inv * sc.w + bi.w;
    ((float4*)(out + (size_t)t * DD))[tid] = o;
}

// ---------------- launch ----------------
extern "C" void kernel_launch(void* const* d_in, const int* in_sizes, int n_in,
                              void* d_out, int out_size) {
    (void)in_sizes; (void)n_in; (void)out_size;
    const float* xs   = (const float*)d_in[0];
    const float* hini = (const float*)d_in[1];
    const float* Wir  = (const float*)d_in[2];
    const float* Wiz  = (const float*)d_in[3];
    const float* Win  = (const float*)d_in[4];
    const float* bir  = (const float*)d_in[5];
    const float* biz  = (const float*)d_in[6];
    const float* bin_ = (const float*)d_in[7];
    const float* Whr  = (const float*)d_in[8];
    const float* Whz  = (const float*)d_in[9];
    const float* Whn  = (const float*)d_in[10];
    const float* bhn  = (const float*)d_in[11];
    const float* Wl   = (const float*)d_in[12];
    const float* bl   = (const float*)d_in[13];
    const float* lns  = (const float*)d_in[14];
    const float* lnb  = (const float*)d_in[15];
    float* out = (float*)d_out;

    float *Ar, *Az, *An, *ys, *lin, *hb;
    unsigned* cnt;
    cudaGetSymbolAddress((void**)&Ar,  g_Ar);
    cudaGetSymbolAddress((void**)&Az,  g_Az);
    cudaGetSymbolAddress((void**)&An,  g_An);
    cudaGetSymbolAddress((void**)&ys,  g_ys);
    cudaGetSymbolAddress((void**)&lin, g_lin);
    cudaGetSymbolAddress((void**)&hb,  g_h);
    cudaGetSymbolAddress((void**)&cnt, g_count);

    // per-replay state reset (device globals persist across graph replays!)
    cudaMemsetAsync(cnt, 0, sizeof(unsigned), 0);
    cudaMemcpyAsync(hb, hini, DD * sizeof(float), cudaMemcpyDeviceToDevice, 0);

    // input projections (bias fused)
    dim3 grid(DD / 128, TT / 128);
    sgemm_kernel<false, false><<<grid, 256>>>(xs, Wir, bir,  nullptr, Ar, TT, DD, DD);
    sgemm_kernel<false, false><<<grid, 256>>>(xs, Wiz, biz,  nullptr, Az, TT, DD, DD);
    sgemm_kernel<false, false><<<grid, 256>>>(xs, Win, bin_, nullptr, An, TT, DD, DD);

    // persistent scan
    const int smem = (3 * 8 * DD + DD) * (int)sizeof(float);  // 102400 B
    cudaFuncSetAttribute(scan_kernel, cudaFuncAttributeMaxDynamicSharedMemorySize, smem);
    scan_kernel<<<NCTA, STH, smem>>>(Whr, Whz, Whn, bhn);

    // out dense: lin = xs + relu(ys)@Wl + bl, then LN
    sgemm_kernel<true, true><<<grid, 256>>>(ys, Wl, bl, xs, lin, TT, DD, DD);
    ln_kernel<<<TT, 256>>>(lin, lns, lnb, out);
}

// round 5
// speedup vs baseline: 1.3260x; 1.3224x over previous
#include <cuda_runtime.h>
#include <math.h>

#define TT 4096
#define DD 1024
#define NCTA 128
#define STH 256   // scan threads: 8 warps, 1 warp per output column (8 cols/CTA)

// ---------------- scratch (device globals: no allocation allowed) ----------------
__device__ float g_Ar[TT * DD];   // xs@Wir + bir
__device__ float g_Az[TT * DD];   // xs@Wiz + biz
__device__ float g_An[TT * DD];   // xs@Win + bin
__device__ float g_ys[TT * DD];   // scan outputs
__device__ float g_lin[TT * DD];  // xs + relu(ys)@Wl + bl (pre-LN)
__device__ float g_h[2][DD];      // ping-pong hidden state
__device__ unsigned g_count;      // grid barrier counter

// ---------------- helpers ----------------
__device__ __forceinline__ float4 ldcg4(const float4* p) {
    float4 v;
    asm volatile("ld.global.cg.v4.f32 {%0,%1,%2,%3}, [%4];"
                 : "=f"(v.x), "=f"(v.y), "=f"(v.z), "=f"(v.w) : "l"(p));
    return v;
}
__device__ __forceinline__ unsigned ld_acquire_u32(const unsigned* p) {
    unsigned v;
    asm volatile("ld.acquire.gpu.global.u32 %0, [%1];" : "=r"(v) : "l"(p));
    return v;
}
__device__ __forceinline__ void red_release_add(unsigned* p) {
    asm volatile("red.release.gpu.global.add.u32 [%0], 1;" :: "l"(p) : "memory");
}

// ---------------- persistent GRU scan ----------------
// 128 CTAs, each owns 8 columns j = cta*8 + w (one warp per column, all 3 gates).
// Recurrent weight columns are REGISTER-RESIDENT: each lane holds 24 float4
// (3 gates x 8 k-chunks). Only h (4KB) goes through SMEM each step.
__global__ void __launch_bounds__(STH, 1) scan_kernel(
    const float* __restrict__ Whr, const float* __restrict__ Whz,
    const float* __restrict__ Whn, const float* __restrict__ bhn)
{
    __shared__ float hs[DD];
    float4* hs4v = (float4*)hs;

    const int tid   = threadIdx.x;
    const int cta   = blockIdx.x;
    const int w     = tid >> 5;
    const int lane  = tid & 31;
    const int j     = cta * 8 + w;

    // one-time weight load into registers: lane covers k = 4*(lane + 32*i) .. +3
    float4 wr[8], wz[8], wn[8];
    #pragma unroll
    for (int i = 0; i < 8; ++i) {
        const int k = 4 * (lane + 32 * i);
        wr[i] = make_float4(Whr[(size_t)(k + 0) * DD + j], Whr[(size_t)(k + 1) * DD + j],
                            Whr[(size_t)(k + 2) * DD + j], Whr[(size_t)(k + 3) * DD + j]);
        wz[i] = make_float4(Whz[(size_t)(k + 0) * DD + j], Whz[(size_t)(k + 1) * DD + j],
                            Whz[(size_t)(k + 2) * DD + j], Whz[(size_t)(k + 3) * DD + j]);
        wn[i] = make_float4(Whn[(size_t)(k + 0) * DD + j], Whn[(size_t)(k + 1) * DD + j],
                            Whn[(size_t)(k + 2) * DD + j], Whn[(size_t)(k + 3) * DD + j]);
    }
    const float bh = bhn[j];

    // prefetch input-projection terms for t=0 (lane 0 only)
    float ar = 0.f, az = 0.f, an = 0.f;
    if (lane == 0) {
        ar = g_Ar[j];
        az = g_Az[j];
        an = g_An[j];
    }

    for (int t = 0; t < TT; ++t) {
        // load h (written by all CTAs last step) -> SMEM. MUST bypass L1 (.cg):
        // L1 may hold a stale copy of this ping-pong buffer from step t-2.
        hs4v[tid] = ldcg4(((const float4*)g_h[t & 1]) + tid);
        __syncthreads();

        // 3 dot products of length 1024, weights in registers
        float accr = 0.f, accz = 0.f, accn = 0.f;
        #pragma unroll
        for (int i = 0; i < 8; ++i) {
            const float4 hv = hs4v[lane + 32 * i];
            accr = fmaf(hv.x, wr[i].x, fmaf(hv.y, wr[i].y, fmaf(hv.z, wr[i].z, fmaf(hv.w, wr[i].w, accr))));
            accz = fmaf(hv.x, wz[i].x, fmaf(hv.y, wz[i].y, fmaf(hv.z, wz[i].z, fmaf(hv.w, wz[i].w, accz))));
            accn = fmaf(hv.x, wn[i].x, fmaf(hv.y, wn[i].y, fmaf(hv.z, wn[i].z, fmaf(hv.w, wn[i].w, accn))));
        }
        #pragma unroll
        for (int off = 16; off > 0; off >>= 1) {
            accr += __shfl_xor_sync(0xffffffffu, accr, off);
            accz += __shfl_xor_sync(0xffffffffu, accz, off);
            accn += __shfl_xor_sync(0xffffffffu, accn, off);
        }
        if (lane == 0) {
            const float hprev = hs[j];
            const float r  = 1.f / (1.f + __expf(-(ar + accr)));
            const float z  = 1.f / (1.f + __expf(-(az + accz)));
            const float n  = tanhf(an + r * (accn + bh));
            const float hn = (1.f - z) * n + z * hprev;
            g_h[(t + 1) & 1][j] = hn;
            g_ys[(size_t)t * DD + j] = hn;
            if (t + 1 < TT) {           // prefetch next step's A terms; the loads
                const size_t o = (size_t)(t + 1) * DD + j;  // complete during the barrier
                ar = g_Ar[o];
                az = g_Az[o];
                an = g_An[o];
            }
        }
        __syncthreads();               // all CTA h writes done + hs reads done

        // grid barrier: release-add, acquire-spin
        if (tid == 0) {
            red_release_add(&g_count);
            const unsigned target = (unsigned)(t + 1) * NCTA;
            while (ld_acquire_u32(&g_count) < target) { }
        }
        __syncthreads();
    }
}

// ---------------- fp32 SGEMM: C[M,N] = op(A)[M,K] @ B[K,N] + bias (+ resid) ----------------
// 128x128 tile, BK=8, 256 threads, 8x8 micro-tile. op = optional relu on A.
// blockIdx.z selects among up to 3 (B, bias, C) triples (fused multi-GEMM).
template <bool RELU, bool RESID>
__global__ void __launch_bounds__(256) sgemm_kernel(
    const float* __restrict__ A,
    const float* __restrict__ B0, const float* __restrict__ B1, const float* __restrict__ B2,
    const float* __restrict__ bias0, const float* __restrict__ bias1, const float* __restrict__ bias2,
    const float* __restrict__ resid,
    float* __restrict__ C0, float* __restrict__ C1, float* __restrict__ C2,
    int M, int N, int K)
{
    const int z = blockIdx.z;
    const float* B    = (z == 0) ? B0    : (z == 1) ? B1    : B2;
    const float* bias = (z == 0) ? bias0 : (z == 1) ? bias1 : bias2;
    float*       C    = (z == 0) ? C0    : (z == 1) ? C1    : C2;

    __shared__ float As[8][128];
    __shared__ float Bs[8][128];
    const int tid = threadIdx.x;
    const int bx = blockIdx.x, by = blockIdx.y;

    const int arow = tid >> 1;         // 0..127
    const int acol = (tid & 1) << 2;   // 0 or 4
    const int brow = tid >> 5;         // 0..7
    const int bcol = (tid & 31) << 2;  // 0..124
    const int tx = tid & 15;
    const int ty = tid >> 4;

    const float* Ab = A + (size_t)by * 128 * K;
    const float* Bb = B + bx * 128;

    float acc[8][8];
    #pragma unroll
    for (int i = 0; i < 8; ++i)
        #pragma unroll
        for (int jj = 0; jj < 8; ++jj) acc[i][jj] = 0.f;

    float4 aReg = *(const float4*)(Ab + (size_t)arow * K + acol);
    float4 bReg = *(const float4*)(Bb + (size_t)brow * N + bcol);

    for (int k0 = 0; k0 < K; k0 += 8) {
        float4 av = aReg;
        if (RELU) {
            av.x = fmaxf(av.x, 0.f); av.y = fmaxf(av.y, 0.f);
            av.z = fmaxf(av.z, 0.f); av.w = fmaxf(av.w, 0.f);
        }
        As[acol + 0][arow] = av.x;
        As[acol + 1][arow] = av.y;
        As[acol + 2][arow] = av.z;
        As[acol + 3][arow] = av.w;
        *(float4*)&Bs[brow][bcol] = bReg;
        __syncthreads();
        if (k0 + 8 < K) {   // prefetch next tile during compute
            aReg = *(const float4*)(Ab + (size_t)arow * K + (k0 + 8) + acol);
            bReg = *(const float4*)(Bb + (size_t)(k0 + 8 + brow) * N + bcol);
        }
        #pragma unroll
        for (int kk = 0; kk < 8; ++kk) {
            float a[8], b[8];
            *(float4*)&a[0] = *(const float4*)&As[kk][ty * 8];
            *(float4*)&a[4] = *(const float4*)&As[kk][ty * 8 + 4];
            *(float4*)&b[0] = *(const float4*)&Bs[kk][tx * 8];
            *(float4*)&b[4] = *(const float4*)&Bs[kk][tx * 8 + 4];
            #pragma unroll
            for (int i = 0; i < 8; ++i)
                #pragma unroll
                for (int jj = 0; jj < 8; ++jj)
                    acc[i][jj] = fmaf(a[i], b[jj], acc[i][jj]);
        }
        __syncthreads();
    }

    const int nbase = bx * 128 + tx * 8;
    const float4 b0 = *(const float4*)(bias + nbase);
    const float4 b1 = *(const float4*)(bias + nbase + 4);
    #pragma unroll
    for (int i = 0; i < 8; ++i) {
        const int m = by * 128 + ty * 8 + i;
        float4 c0, c1;
        c0.x = acc[i][0] + b0.x; c0.y = acc[i][1] + b0.y;
        c0.z = acc[i][2] + b0.z; c0.w = acc[i][3] + b0.w;
        c1.x = acc[i][4] + b1.x; c1.y = acc[i][5] + b1.y;
        c1.z = acc[i][6] + b1.z; c1.w = acc[i][7] + b1.w;
        if (RESID) {
            const float4 r0 = *(const float4*)(resid + (size_t)m * N + nbase);
            const float4 r1 = *(const float4*)(resid + (size_t)m * N + nbase + 4);
            c0.x += r0.x; c0.y += r0.y; c0.z += r0.z; c0.w += r0.w;
            c1.x += r1.x; c1.y += r1.y; c1.z += r1.z; c1.w += r1.w;
        }
        *(float4*)(C + (size_t)m * N + nbase)     = c0;
        *(float4*)(C + (size_t)m * N + nbase + 4) = c1;
    }
}

// ---------------- layernorm over last dim ----------------
__global__ void __launch_bounds__(256) ln_kernel(
    const float* __restrict__ lin, const float* __restrict__ scale,
    const float* __restrict__ bias, float* __restrict__ out)
{
    const int t = blockIdx.x;
    const int tid = threadIdx.x;
    const int w = tid >> 5, lane = tid & 31;
    const float4 v = ((const float4*)(lin + (size_t)t * DD))[tid];
    float s = v.x + v.y + v.z + v.w;
    float q = v.x * v.x + v.y * v.y + v.z * v.z + v.w * v.w;
    #pragma unroll
    for (int off = 16; off > 0; off >>= 1) {
        s += __shfl_xor_sync(0xffffffffu, s, off);
        q += __shfl_xor_sync(0xffffffffu, q, off);
    }
    __shared__ float ss[8], qs[8];
    __shared__ float sMean, sInv;
    if (lane == 0) { ss[w] = s; qs[w] = q; }
    __syncthreads();
    if (tid == 0) {
        float S = 0.f, Q = 0.f;
        #pragma unroll
        for (int i = 0; i < 8; ++i) { S += ss[i]; Q += qs[i]; }
        const float mean = S * (1.0f / DD);
        const float var  = Q * (1.0f / DD) - mean * mean;
        sMean = mean;
        sInv  = rsqrtf(var + 1e-6f);
    }
    __syncthreads();
    const float mean = sMean, inv = sInv;
    const float4 sc = ((const float4*)scale)[tid];
    const float4 bi = ((const float4*)bias)[tid];
    float4 o;
    o.x = (v.x - mean) * inv * sc.x + bi.x;
    o.y = (v.y - mean) * inv * sc.y + bi.y;
    o.z = (v.z - mean) * inv * sc.z + bi.z;
    o.w = (v.w - mean) * inv * sc.w + bi.w;
    ((float4*)(out + (size_t)t * DD))[tid] = o;
}

// ---------------- launch ----------------
extern "C" void kernel_launch(void* const* d_in, const int* in_sizes, int n_in,
                              void* d_out, int out_size) {
    (void)in_sizes; (void)n_in; (void)out_size;
    const float* xs   = (const float*)d_in[0];
    const float* hini = (const float*)d_in[1];
    const float* Wir  = (const float*)d_in[2];
    const float* Wiz  = (const float*)d_in[3];
    const float* Win  = (const float*)d_in[4];
    const float* bir  = (const float*)d_in[5];
    const float* biz  = (const float*)d_in[6];
    const float* bin_ = (const float*)d_in[7];
    const float* Whr  = (const float*)d_in[8];
    const float* Whz  = (const float*)d_in[9];
    const float* Whn  = (const float*)d_in[10];
    const float* bhn  = (const float*)d_in[11];
    const float* Wl   = (const float*)d_in[12];
    const float* bl   = (const float*)d_in[13];
    const float* lns  = (const float*)d_in[14];
    const float* lnb  = (const float*)d_in[15];
    float* out = (float*)d_out;

    float *Ar, *Az, *An, *ys, *lin, *hb;
    unsigned* cnt;
    cudaGetSymbolAddress((void**)&Ar,  g_Ar);
    cudaGetSymbolAddress((void**)&Az,  g_Az);
    cudaGetSymbolAddress((void**)&An,  g_An);
    cudaGetSymbolAddress((void**)&ys,  g_ys);
    cudaGetSymbolAddress((void**)&lin, g_lin);
    cudaGetSymbolAddress((void**)&hb,  g_h);
    cudaGetSymbolAddress((void**)&cnt, g_count);

    // per-replay state reset (device globals persist across graph replays!)
    cudaMemsetAsync(cnt, 0, sizeof(unsigned), 0);
    cudaMemcpyAsync(hb, hini, DD * sizeof(float), cudaMemcpyDeviceToDevice, 0);

    // input projections (bias fused), all three in one launch via grid.z
    dim3 grid3(DD / 128, TT / 128, 3);
    sgemm_kernel<false, false><<<grid3, 256>>>(
        xs, Wir, Wiz, Win, bir, biz, bin_, nullptr, Ar, Az, An, TT, DD, DD);

    // persistent scan (weights register-resident; 4KB static smem for h)
    scan_kernel<<<NCTA, STH>>>(Whr, Whz, Whn, bhn);

    // out dense: lin = xs + relu(ys)@Wl + bl, then LN
    dim3 grid1(DD / 128, TT / 128, 1);
    sgemm_kernel<true, true><<<grid1, 256>>>(
        ys, Wl, nullptr, nullptr, bl, nullptr, nullptr, xs, lin, nullptr, nullptr, TT, DD, DD);
    ln_kernel<<<TT, 256>>>(lin, lns, lnb, out);
}